// round 13
// baseline (speedup 1.0000x reference)
#include <cuda_runtime.h>
#include <cuda_bf16.h>
#include <math.h>
#include <stdint.h>

// Problem constants
#define BB   2
#define LL   2048
#define DD   1024
#define HH   16
#define HD   64
#define MM   (BB*LL)          // 4096

// Scratch (static device memory -- no allocations allowed)
__device__ float g_RT[DD * DD];           // R^T
__device__ float g_WT[3 * DD * DD];       // W_i^T
// fp16 fragment-layout K/V: per (b,h,chunk64) 32 blocks of 256B
__device__ uint32_t g_Kh[BB * HH * 32 * 32 * 64];   // 8MB
__device__ uint32_t g_Vh[BB * HH * 32 * 32 * 64];   // 8MB
// Q in attention A-fragment order: (tile16 0..255, colblk 0..63) x 128 words
__device__ uint32_t g_Qpk[256 * 64 * 128];          // 8MB
// packed GEMM operands
__device__ uint32_t g_Xpk [32 * 32 * 2048];   // X packed f16 (8MB)
__device__ uint32_t g_AOpk[32 * 32 * 2048];   // attention out packed f16 (8MB)
__device__ uint32_t g_Wfpk[24 * 32 * 4096];   // folded W packed hi/lo f16 (12MB)
__device__ uint32_t g_Wopk[ 8 * 32 * 4096];   // Wo packed hi/lo f16 (4MB)

// ===========================================================================
// helpers
// ===========================================================================
__device__ __forceinline__ uint32_t pkf16(float lo, float hi) {
    uint32_t r;
    asm("cvt.rn.f16x2.f32 %0, %1, %2;" : "=r"(r) : "f"(hi), "f"(lo));
    return r;
}

__device__ __forceinline__ void unpkf16(float& lo, float& hi, uint32_t w) {
    asm("{.reg .b16 l, h; mov.b32 {l, h}, %2; cvt.f32.f16 %0, l; cvt.f32.f16 %1, h;}"
        : "=f"(lo), "=f"(hi) : "r"(w));
}

// split two fp32 -> (hi f16x2 word, lo f16x2 word)
__device__ __forceinline__ uint2 split2h(float a, float b) {
    uint32_t h = pkf16(a, b);
    float f0, f1;
    unpkf16(f0, f1, h);
    uint32_t l = pkf16(a - f0, b - f1);
    return make_uint2(h, l);
}

// split fp32x4 -> (hi pair, lo pair)  (pack kernels)
__device__ __forceinline__ uint4 split4h(float4 v) {
    uint32_t h01 = pkf16(v.x, v.y);
    uint32_t h23 = pkf16(v.z, v.w);
    float f0, f1, f2, f3;
    unpkf16(f0, f1, h01);
    unpkf16(f2, f3, h23);
    uint32_t l01 = pkf16(v.x - f0, v.y - f1);
    uint32_t l23 = pkf16(v.z - f2, v.w - f3);
    return make_uint4(h01, h23, l01, l23);
}

// bf16 split (fold GEMM operands)
__device__ __forceinline__ uint4 split4(float4 v) {
    uint32_t h01, h23;
    asm("cvt.rn.bf16x2.f32 %0, %1, %2;" : "=r"(h01) : "f"(v.y), "f"(v.x));
    asm("cvt.rn.bf16x2.f32 %0, %1, %2;" : "=r"(h23) : "f"(v.w), "f"(v.z));
    float h0 = __uint_as_float(h01 << 16);
    float h1 = __uint_as_float(h01 & 0xFFFF0000u);
    float h2 = __uint_as_float(h23 << 16);
    float h3 = __uint_as_float(h23 & 0xFFFF0000u);
    uint32_t l01, l23;
    asm("cvt.rn.bf16x2.f32 %0, %1, %2;" : "=r"(l01) : "f"(v.y - h1), "f"(v.x - h0));
    asm("cvt.rn.bf16x2.f32 %0, %1, %2;" : "=r"(l23) : "f"(v.w - h3), "f"(v.z - h2));
    return make_uint4(h01, h23, l01, l23);
}

__device__ __forceinline__ void mma16816(float* c,
                                         uint32_t a0, uint32_t a1, uint32_t a2, uint32_t a3,
                                         uint32_t b0, uint32_t b1) {
    asm volatile(
        "mma.sync.aligned.m16n8k16.row.col.f32.bf16.bf16.f32 "
        "{%0,%1,%2,%3}, {%4,%5,%6,%7}, {%8,%9}, {%0,%1,%2,%3};"
        : "+f"(c[0]), "+f"(c[1]), "+f"(c[2]), "+f"(c[3])
        : "r"(a0), "r"(a1), "r"(a2), "r"(a3), "r"(b0), "r"(b1));
}

__device__ __forceinline__ void mma16816h(float* c,
                                          uint32_t a0, uint32_t a1, uint32_t a2, uint32_t a3,
                                          uint32_t b0, uint32_t b1) {
    asm volatile(
        "mma.sync.aligned.m16n8k16.row.col.f32.f16.f16.f32 "
        "{%0,%1,%2,%3}, {%4,%5,%6,%7}, {%8,%9}, {%0,%1,%2,%3};"
        : "+f"(c[0]), "+f"(c[1]), "+f"(c[2]), "+f"(c[3])
        : "r"(a0), "r"(a1), "r"(a2), "r"(a3), "r"(b0), "r"(b1));
}

__device__ __forceinline__ float ex2(float x) {
    float r;
    asm("ex2.approx.f32 %0, %1;" : "=f"(r) : "f"(x));
    return r;
}

__device__ __forceinline__ uint32_t ex2h2(uint32_t x) {
    uint32_t r;
    asm("ex2.approx.f16x2 %0, %1;" : "=r"(r) : "r"(x));
    return r;
}

__device__ __forceinline__ uint32_t smem_u32(const void* p) {
    uint32_t a;
    asm("{ .reg .u64 t; cvta.to.shared.u64 t, %1; cvt.u32.u64 %0, t; }"
        : "=r"(a) : "l"(p));
    return a;
}

__device__ __forceinline__ void cp_async16(uint32_t dst, const void* src) {
    asm volatile("cp.async.cg.shared.global [%0], [%1], 16;"
                 :: "r"(dst), "l"(src) : "memory");
}

// ===========================================================================
// Operand pack kernels (inputs only: X and Wo)
// ===========================================================================
__global__ __launch_bounds__(256)
void pack_a_kernel(const float* __restrict__ src, uint32_t* __restrict__ dst)
{
    const int kpair = blockIdx.x, mtile = blockIdx.y, tid = threadIdx.x;
    uint32_t* region = dst + ((size_t)mtile * 32 + kpair) * 2048;
#pragma unroll
    for (int i = 0; i < 4; i++) {
        int idx = i * 256 + tid;
        int row = idx >> 3, c4 = (idx & 7) << 2;
        float4 v = *reinterpret_cast<const float4*>(
            &src[(size_t)(mtile * 128 + row) * 1024 + kpair * 32 + c4]);
        uint32_t w0 = pkf16(v.x, v.y);
        uint32_t w1 = pkf16(v.z, v.w);
        int mb = row >> 4, r = row & 7;
        int islow = ((row & 15) < 8);
        int kb = c4 >> 4, kk = c4 & 15;
        int khigh = (kk >> 3) & 1, t = (kk & 7) >> 1;
        uint32_t* base = region + (mb * 2 + kb) * 128;
        int aidx = islow ? (khigh ? 2 : 0) : (khigh ? 3 : 1);
        base[(r * 4 + t)     * 4 + aidx] = w0;
        base[(r * 4 + t + 1) * 4 + aidx] = w1;
    }
}

__global__ __launch_bounds__(256)
void pack_b_kernel(const float* __restrict__ src, uint32_t* __restrict__ dst)
{
    const int kpair = blockIdx.x, ntile = blockIdx.y, tid = threadIdx.x;
    uint32_t* region = dst + ((size_t)ntile * 32 + kpair) * 4096;
#pragma unroll
    for (int i = 0; i < 4; i++) {
        int idx = i * 256 + tid;
        int row = idx >> 3, c4 = (idx & 7) << 2;
        float4 v = *reinterpret_cast<const float4*>(
            &src[(size_t)(ntile * 128 + row) * 1024 + kpair * 32 + c4]);
        uint4 sp = split4h(v);
        int nb = row >> 3;
        int kb = c4 >> 4, kk = c4 & 15;
        int khigh = (kk >> 3) & 1, t = (kk & 7) >> 1;
        int L = ((row & 7) << 2) + t;
        uint32_t* base = region + (nb * 2 + kb) * 128;
        base[L * 2 + khigh]            = sp.x;
        base[(L + 1) * 2 + khigh]      = sp.y;
        base[64 + L * 2 + khigh]       = sp.z;
        base[64 + (L + 1) * 2 + khigh] = sp.w;
    }
}

// ===========================================================================
// Packed 2-pass f16 GEMM v3: C[M,N] = A @ (Bhi+Blo)^T, K=1024.
// CTA tile 128x256, 8 warps (2x4) of 64x64, BK=32, double-buffered, 1 CTA/SM.
// Tensor-bound: 128 MMA/warp/chunk vs 12KB LDS/warp/chunk.
// mode 0: fp32 C epilogue; mode 1: QKV fused epilogue -> Qpk/Kh/Vh.
// ===========================================================================
#define PKG_CHUNK 40960              // 8KB A + 2x16KB B regions
#define PKG_SMEM  (2 * PKG_CHUNK)    // 81920

__global__ __launch_bounds__(256, 1)
void pk_gemm(const uint32_t* __restrict__ A, const uint32_t* __restrict__ B,
             float* __restrict__ C, int ldc, int mode,
             uint32_t* __restrict__ Qpk, uint32_t* __restrict__ Kh,
             uint32_t* __restrict__ Vh)
{
    extern __shared__ char sm[];
    const uint32_t sb = smem_u32(sm);
    const int tid  = threadIdx.x;
    const int lane = tid & 31;
    const int wid  = tid >> 5;
    const int wm   = (wid >> 2) * 64;          // 0 or 64
    const int wn   = (wid & 3) * 64;           // 0,64,128,192
    const int wreg = wn >> 7;                  // B region for this warp
    const int wnb  = (wn & 127) >> 3;          // base nb within region

    const char* Ag  = reinterpret_cast<const char*>(A + (size_t)blockIdx.y * 32 * 2048);
    const char* Bg0 = reinterpret_cast<const char*>(B + (size_t)(blockIdx.x * 2) * 32 * 4096);
    const char* Bg1 = reinterpret_cast<const char*>(B + (size_t)(blockIdx.x * 2 + 1) * 32 * 4096);

    float acc[4][8][4];
#pragma unroll
    for (int i = 0; i < 4; i++)
#pragma unroll
        for (int j = 0; j < 8; j++)
#pragma unroll
            for (int q = 0; q < 4; q++) acc[i][j][q] = 0.f;

#define PKG_PF(ch)                                                             \
    {                                                                          \
        uint32_t d = sb + ((ch) & 1) * PKG_CHUNK;                              \
        const char* a  = Ag  + (size_t)(ch) * 8192  + tid * 32;                \
        const char* b0 = Bg0 + (size_t)(ch) * 16384 + tid * 64;                \
        const char* b1 = Bg1 + (size_t)(ch) * 16384 + tid * 64;                \
        cp_async16(d + tid * 32,      a);                                      \
        cp_async16(d + tid * 32 + 16, a + 16);                                 \
        uint32_t db0 = d + 8192 + tid * 64;                                    \
        cp_async16(db0,      b0);                                              \
        cp_async16(db0 + 16, b0 + 16);                                         \
        cp_async16(db0 + 32, b0 + 32);                                         \
        cp_async16(db0 + 48, b0 + 48);                                         \
        uint32_t db1 = d + 24576 + tid * 64;                                   \
        cp_async16(db1,      b1);                                              \
        cp_async16(db1 + 16, b1 + 16);                                         \
        cp_async16(db1 + 32, b1 + 32);                                         \
        cp_async16(db1 + 48, b1 + 48);                                         \
        asm volatile("cp.async.commit_group;" ::: "memory");                   \
    }

    PKG_PF(0);

    for (int ch = 0; ch < 32; ch++) {
        if (ch < 31) {
            PKG_PF(ch + 1);
            asm volatile("cp.async.wait_group 1;" ::: "memory");
        } else {
            asm volatile("cp.async.wait_group 0;" ::: "memory");
        }
        __syncthreads();

        const char* bufA = sm + (ch & 1) * PKG_CHUNK;
        const char* bufB = bufA + 8192 + wreg * 16384;
#pragma unroll
        for (int kb = 0; kb < 2; kb++) {
            uint4 ah[4];
            uint2 bh[8], bl[8];
#pragma unroll
            for (int am = 0; am < 4; am++) {
                const char* p = bufA + ((((wm >> 4) + am) * 2 + kb) << 9) + lane * 16;
                ah[am] = *(const uint4*)p;
            }
#pragma unroll
            for (int bn = 0; bn < 8; bn++) {
                const char* q = bufB + (((wnb + bn) * 2 + kb) << 9) + lane * 8;
                bh[bn] = *(const uint2*)q;
                bl[bn] = *(const uint2*)(q + 256);
            }
#pragma unroll
            for (int am = 0; am < 4; am++)
#pragma unroll
                for (int bn = 0; bn < 8; bn++) {
                    float* c = acc[am][bn];
                    mma16816h(c, ah[am].x, ah[am].y, ah[am].z, ah[am].w,
                              bh[bn].x, bh[bn].y);
                    mma16816h(c, ah[am].x, ah[am].y, ah[am].z, ah[am].w,
                              bl[bn].x, bl[bn].y);
                }
        }
        if (ch < 31) __syncthreads();
    }

    const int m0 = blockIdx.y * 128;
    const int n0 = blockIdx.x * 256;

    if (mode == 0) {
#pragma unroll
        for (int am = 0; am < 4; am++)
#pragma unroll
            for (int bn = 0; bn < 8; bn++) {
                const float* c = acc[am][bn];
                int row = m0 + wm + am * 16 + (lane >> 2);
                int col = n0 + wn + bn * 8 + ((lane & 3) << 1);
                *reinterpret_cast<float2*>(&C[(size_t)row * ldc + col]) =
                    make_float2(c[0], c[1]);
                *reinterpret_cast<float2*>(&C[(size_t)(row + 8) * ldc + col]) =
                    make_float2(c[2], c[3]);
            }
    } else if (blockIdx.x < 4) {
        // ---- Q: f16 A-fragment words (scale folded into weights) ----
#pragma unroll
        for (int am = 0; am < 4; am++)
#pragma unroll
            for (int bn = 0; bn < 8; bn++) {
                const float* c = acc[am][bn];
                int row = m0 + wm + am * 16 + (lane >> 2);
                int col = n0 + wn + bn * 8 + ((lane & 3) << 1);   // 0..1023
                size_t t16 = (size_t)(row >> 4);
                int cb = col >> 4;
                int bhf = (col >> 3) & 1;
                uint32_t* qd = Qpk + (t16 * 64 + cb) * 128 + lane * 4 + bhf * 2;
                qd[0] = pkf16(c[0], c[1]);
                qd[1] = pkf16(c[2], c[3]);
            }
    } else if (blockIdx.x < 8) {
        // ---- K: attention B-fragment words ----
#pragma unroll
        for (int am = 0; am < 4; am++)
#pragma unroll
            for (int bn = 0; bn < 8; bn++) {
                const float* c = acc[am][bn];
                int row = m0 + wm + am * 16 + (lane >> 2);
                int col = n0 + wn + bn * 8 + ((lane & 3) << 1);
                int bq = row >> 11, seq = row & 2047;
                int chh = seq >> 6, keyl = seq & 63;
                int nk = col - 1024, hh = nk >> 6, d = nk & 63;
                size_t grp = ((size_t)(bq * HH + hh) * 32 + chh) * 32;
                int w = (d >> 3) & 1;
                int L = ((keyl & 7) << 2) | ((d >> 1) & 3);
                Kh[(grp + (keyl >> 3) * 4 + (d >> 4)) * 64 + L * 2 + w] =
                    pkf16(c[0], c[1]);
                Kh[(grp + ((keyl >> 3) + 1) * 4 + (d >> 4)) * 64 + L * 2 + w] =
                    pkf16(c[2], c[3]);
            }
    } else {
        // ---- V: (key, key+1) pairs via shfl_xor(4) ----
#pragma unroll
        for (int am = 0; am < 4; am++)
#pragma unroll
            for (int bn = 0; bn < 8; bn++) {
                const float* c = acc[am][bn];
                float p0 = __shfl_xor_sync(0xffffffffu, c[0], 4);
                float p1 = __shfl_xor_sync(0xffffffffu, c[1], 4);
                float p2 = __shfl_xor_sync(0xffffffffu, c[2], 4);
                float p3 = __shfl_xor_sync(0xffffffffu, c[3], 4);
                if (!(lane & 4)) {
                    int row = m0 + wm + am * 16 + (lane >> 2);
                    int col = n0 + wn + bn * 8 + ((lane & 3) << 1);
                    int bq = row >> 11, seq = row & 2047;
                    int chh = seq >> 6, keyl = seq & 63;
                    int nv = col - 2048, hh = nv >> 6, d = nv & 63;
                    size_t grp = ((size_t)(bq * HH + hh) * 32 + chh) * 32;
                    int kp = keyl >> 1;
                    int L = ((d & 7) << 2) | (kp & 3);
                    int w = (kp & 7) >> 2;
                    size_t blk = (grp + (d >> 3) * 4 + (keyl >> 4)) * 64;
                    Vh[blk + L * 2 + w]             = pkf16(c[0], p0);
                    Vh[blk + (L + 4) * 2 + w]       = pkf16(c[1], p1);
                    Vh[blk + L * 2 + (w ^ 1)]       = pkf16(c[2], p2);
                    Vh[blk + (L + 4) * 2 + (w ^ 1)] = pkf16(c[3], p3);
                }
            }
    }
#undef PKG_PF
}

// ===========================================================================
// Fold GEMM (convert-in-kernel split-bf16): C = R^T W_i, epilogue writes
// split-f16 packed-B words directly; Wq rows get the softmax scale folded in.
// ===========================================================================
#define TCB_SMEM 65536

__global__ __launch_bounds__(256, 1)
void fold_gemm_kernel(const float* __restrict__ A, const float* __restrict__ B,
                      uint32_t* __restrict__ Bpk, const float* __restrict__ ent,
                      size_t sB)
{
    extern __shared__ char sm[];
    B += blockIdx.z * sB;
    const int tid  = threadIdx.x;
    const int lane = tid & 31;
    const int wid  = tid >> 5;
    const int wm   = (wid >> 2) * 64;
    const int wn   = (wid & 3) * 32;
    const int m0 = blockIdx.y * 128;
    const int n0 = blockIdx.x * 128;
    const int pl = lane ^ (lane >> 3);

    float acc[4][4][4];
#pragma unroll
    for (int i = 0; i < 4; i++)
#pragma unroll
        for (int j = 0; j < 4; j++)
#pragma unroll
            for (int q = 0; q < 4; q++) acc[i][j][q] = 0.f;

    float4 ra[4], rb[4];

#define LDG_CHUNK(k0)                                                          \
    {                                                                          \
        _Pragma("unroll")                                                      \
        for (int i = 0; i < 4; i++) {                                          \
            int idx = i * 256 + tid;                                           \
            int r = idx >> 3, c4 = (idx & 7) << 2;                             \
            ra[i] = *reinterpret_cast<const float4*>(                          \
                &A[(size_t)(m0 + r) * 1024 + (k0) + c4]);                      \
            rb[i] = *reinterpret_cast<const float4*>(                          \
                &B[(size_t)(n0 + r) * 1024 + (k0) + c4]);                      \
        }                                                                      \
    }

#define STS_CHUNK(bufp)                                                        \
    {                                                                          \
        char* _buf = (bufp);                                                   \
        _Pragma("unroll")                                                      \
        for (int i = 0; i < 4; i++) {                                          \
            int idx = i * 256 + tid;                                           \
            int r = idx >> 3, c4 = (idx & 7) << 2;                             \
            int kb = c4 >> 4, kk = c4 & 15;                                    \
            int rr = r & 15, mb = r >> 4;                                      \
            int s  = ((rr & 7) << 2) + ((kk & 7) >> 1);                        \
            int ps  = s ^ (s >> 3);                                            \
            int ps1 = (s + 1) ^ ((s + 1) >> 3);                                \
            int rg = (kk >> 3) + ((rr >> 3) << 1);                             \
            uint4 sp = split4(ra[i]);                                          \
            char* ab = _buf + (((mb << 1) + kb) << 9) + (rg << 2);             \
            *(uint32_t*)(ab + ps  * 16)        = sp.x;                         \
            *(uint32_t*)(ab + ps1 * 16)        = sp.y;                         \
            *(uint32_t*)(ab + 8192 + ps  * 16) = sp.z;                         \
            *(uint32_t*)(ab + 8192 + ps1 * 16) = sp.w;                         \
            int nn = r & 7, nb = r >> 3;                                       \
            int sb2 = (nn << 2) + ((kk & 7) >> 1);                             \
            int psb  = sb2 ^ (sb2 >> 3);                                       \
            int psb1 = (sb2 + 1) ^ ((sb2 + 1) >> 3);                           \
            int rgb = kk >> 3;                                                 \
            uint4 sq = split4(rb[i]);                                          \
            char* bb = _buf + 16384 + (((nb << 1) + kb) << 9) + (rgb << 2);    \
            *(uint32_t*)(bb + psb  * 16)     = sq.x;                           \
            *(uint32_t*)(bb + psb1 * 16)     = sq.y;                           \
            *(uint32_t*)(bb + psb  * 16 + 8) = sq.z;                           \
            *(uint32_t*)(bb + psb1 * 16 + 8) = sq.w;                           \
        }                                                                      \
    }

#define COMPUTE_CHUNK(bufp)                                                    \
    {                                                                          \
        const char* _buf = (bufp);                                             \
        _Pragma("unroll")                                                      \
        for (int kb = 0; kb < 2; kb++) {                                       \
            uint4 ah[4], al[4], bq[4];                                         \
            _Pragma("unroll")                                                  \
            for (int am = 0; am < 4; am++) {                                   \
                const char* p = _buf + (((((wm >> 4) + am) << 1) + kb) << 9)   \
                                + pl * 16;                                     \
                ah[am] = *(const uint4*)p;                                     \
                al[am] = *(const uint4*)(p + 8192);                            \
            }                                                                  \
            _Pragma("unroll")                                                  \
            for (int bn = 0; bn < 4; bn++) {                                   \
                const char* p = _buf + 16384                                   \
                                + (((((wn >> 3) + bn) << 1) + kb) << 9)        \
                                + pl * 16;                                     \
                bq[bn] = *(const uint4*)p;                                     \
            }                                                                  \
            _Pragma("unroll")                                                  \
            for (int am = 0; am < 4; am++)                                     \
                _Pragma("unroll")                                              \
                for (int bn = 0; bn < 4; bn++) {                               \
                    float* c = acc[am][bn];                                    \
                    mma16816(c, ah[am].x, ah[am].z, ah[am].y, ah[am].w,        \
                             bq[bn].x, bq[bn].y);                              \
                    mma16816(c, ah[am].x, ah[am].z, ah[am].y, ah[am].w,        \
                             bq[bn].z, bq[bn].w);                              \
                    mma16816(c, al[am].x, al[am].z, al[am].y, al[am].w,        \
                             bq[bn].x, bq[bn].y);                              \
                }                                                              \
        }                                                                      \
    }

    LDG_CHUNK(0);
    STS_CHUNK(sm);
    __syncthreads();

    for (int ch = 0; ch < 32; ch++) {
        if (ch < 31) LDG_CHUNK((ch + 1) * 32);
        COMPUTE_CHUNK(sm + (ch & 1) * 32768);
        if (ch < 31) {
            STS_CHUNK(sm + ((ch + 1) & 1) * 32768);
            __syncthreads();
        }
    }

    // ---- epilogue: write split-f16 packed-B words (rows = neurons, cols = k)
#pragma unroll
    for (int am = 0; am < 4; am++)
#pragma unroll
        for (int bn = 0; bn < 4; bn++) {
            const float* c = acc[am][bn];
            int row = m0 + wm + am * 16 + (lane >> 2);
            int col = n0 + wn + bn * 8 + ((lane & 3) << 1);
            float s = 1.f;
            if (blockIdx.z == 0) s = ent[row >> 6] * 0.125f * 1.44269504f;
            int ntg = blockIdx.z * 8 + (row >> 7);
            int kpair = col >> 5;
            uint32_t* region = Bpk + ((size_t)ntg * 32 + kpair) * 4096;
            int kb = (col >> 4) & 1;
            int khigh = (col >> 3) & 1;
            int t = (col >> 1) & 3;
            int L = ((row & 7) << 2) + t;
            {
                uint2 u = split2h(c[0] * s, c[1] * s);
                uint32_t* base = region + (((row >> 3) & 15) * 2 + kb) * 128;
                base[L * 2 + khigh]      = u.x;
                base[64 + L * 2 + khigh] = u.y;
            }
            {
                uint2 u = split2h(c[2] * s, c[3] * s);
                uint32_t* base = region + ((((row + 8) >> 3) & 15) * 2 + kb) * 128;
                base[L * 2 + khigh]      = u.x;
                base[64 + L * 2 + khigh] = u.y;
            }
        }
#undef LDG_CHUNK
#undef STS_CHUNK
#undef COMPUTE_CHUNK
}

// ---------------------------------------------------------------------------
// Batched 1024x1024 transpose: z=0 -> RT = R^T; z=1..3 -> WT_i = W_i^T
// ---------------------------------------------------------------------------
__global__ __launch_bounds__(256)
void transpose_kernel(const float* __restrict__ R,
                      const float* __restrict__ Wq,
                      const float* __restrict__ Wk,
                      const float* __restrict__ Wv,
                      float* __restrict__ RT, float* __restrict__ WT)
{
    __shared__ float t[32][33];
    const int z = blockIdx.z;
    const float* src = (z == 0) ? R : (z == 1) ? Wq : (z == 2) ? Wk : Wv;
    float* dst = (z == 0) ? RT : (WT + (size_t)(z - 1) * DD * DD);

    const int x0 = blockIdx.x * 32;
    const int y0 = blockIdx.y * 32;
    const int tx = threadIdx.x & 31;
    const int ty = threadIdx.x >> 5;

#pragma unroll
    for (int i = 0; i < 4; i++)
        t[ty + i * 8][tx] = src[(size_t)(y0 + ty + i * 8) * DD + x0 + tx];
    __syncthreads();
#pragma unroll
    for (int i = 0; i < 4; i++)
        dst[(size_t)(x0 + ty + i * 8) * DD + y0 + tx] = t[tx][ty + i * 8];
}

// ===========================================================================
// Tensor-core flash attention (round-8 pipeline): packed fp16 Q/K/V,
// double buffer, softmax-lite, lazy rescale. Writes f16 packed-A AO.
// ===========================================================================
#define ONES16X2 0x3C003C00u

__global__ __launch_bounds__(256, 2)
void flash_attn_tc2(const uint32_t* __restrict__ Qpk,
                    const uint32_t* __restrict__ Kh,
                    const uint32_t* __restrict__ Vh,
                    uint32_t* __restrict__ AOpk)
{
    __shared__ char sbuf[2 * 16384];
    const uint32_t sb0 = smem_u32(sbuf);

    const int b  = blockIdx.z;
    const int h  = blockIdx.y;
    const int qt = blockIdx.x;
    const int tid  = threadIdx.x;
    const int lane = tid & 31;
    const int wid  = tid >> 5;

    // ---- Q fragments: 4 x LDG.128, already scaled ----
    uint32_t qa[4][4];
    {
        const uint32_t* qbase =
            Qpk + ((size_t)(b * 128 + qt * 8 + wid) * 64 + h * 4) * 128 + lane * 4;
#pragma unroll
        for (int kb = 0; kb < 4; kb++)
            *reinterpret_cast<uint4*>(qa[kb]) =
                *reinterpret_cast<const uint4*>(qbase + kb * 128);
    }

    float oc[8][4];
#pragma unroll
    for (int i = 0; i < 8; i++)
#pragma unroll
        for (int j = 0; j < 4; j++) oc[i][j] = 0.f;
    float l0 = 0.f, l1 = 0.f;
    float mx0 = -1e30f, mx1 = -1e30f;

    const char* Kg = reinterpret_cast<const char*>(Kh)
                     + (size_t)((b * HH + h) * 32) * 8192;
    const char* Vg = reinterpret_cast<const char*>(Vh)
                     + (size_t)((b * HH + h) * 32) * 8192;

#define FA_PREFETCH(ch)                                                        \
    {                                                                          \
        uint32_t d = sb0 + ((ch) & 1) * 16384 + tid * 16;                      \
        const char* ks = Kg + (size_t)(ch) * 8192 + tid * 16;                  \
        const char* vs = Vg + (size_t)(ch) * 8192 + tid * 16;                  \
        cp_async16(d,           ks);                                           \
        cp_async16(d + 4096,    ks + 4096);                                    \
        cp_async16(d + 8192,    vs);                                           \
        cp_async16(d + 12288,   vs + 4096);                                    \
        asm volatile("cp.async.commit_group;" ::: "memory");                   \
    }

    FA_PREFETCH(0);

    for (int ch = 0; ch < 32; ch++) {
        if (ch < 31) {
            FA_PREFETCH(ch + 1);
            asm volatile("cp.async.wait_group 1;" ::: "memory");
        } else {
            asm volatile("cp.async.wait_group 0;" ::: "memory");
        }
        __syncthreads();

        const char* kb_ = sbuf + (ch & 1) * 16384;
        const char* vb_ = kb_ + 8192;

        // ---- QK ----
        float sc[8][4];
#pragma unroll
        for (int nb = 0; nb < 8; nb++) {
            sc[nb][0] = sc[nb][1] = sc[nb][2] = sc[nb][3] = 0.f;
#pragma unroll
            for (int kb = 0; kb < 4; kb++) {
                uint2 bb = *(const uint2*)(kb_ + ((nb << 2) | kb) * 256 + lane * 8);
                mma16816h(sc[nb], qa[kb][0], qa[kb][1], qa[kb][2], qa[kb][3],
                          bb.x, bb.y);
            }
        }

        // ---- max reduce ----
        float cm0 = mx0, cm1 = mx1;
#pragma unroll
        for (int nb = 0; nb < 8; nb++) {
            cm0 = fmaxf(cm0, fmaxf(sc[nb][0], sc[nb][1]));
            cm1 = fmaxf(cm1, fmaxf(sc[nb][2], sc[nb][3]));
        }
        cm0 = fmaxf(cm0, __shfl_xor_sync(0xffffffffu, cm0, 1));
        cm0 = fmaxf(cm0, __shfl_xor_sync(0xffffffffu, cm0, 2));
        cm1 = fmaxf(cm1, __shfl_xor_sync(0xffffffffu, cm1, 1));
        cm1 = fmaxf(cm1, __shfl_xor_sync(0xffffffffu, cm1, 2));

        // ---- lazy rescale ----
        if (__any_sync(0xffffffffu, (cm0 > mx0) || (cm1 > mx1))) {
            float corr0 = ex2(mx0 - cm0), corr1 = ex2(mx1 - cm1);
            mx0 = cm0; mx1 = cm1;
            l0 *= corr0; l1 *= corr1;
#pragma unroll
            for (int nb = 0; nb < 8; nb++) {
                oc[nb][0] *= corr0; oc[nb][1] *= corr0;
                oc[nb][2] *= corr1; oc[nb][3] *= corr1;
            }
        }

        // ---- P fragments via f16x2 ex2 ----
        uint32_t pw0[8], pw1[8];
#pragma unroll
        for (int nb = 0; nb < 8; nb++) {
            pw0[nb] = ex2h2(pkf16(sc[nb][0] - mx0, sc[nb][1] - mx0));
            pw1[nb] = ex2h2(pkf16(sc[nb][2] - mx1, sc[nb][3] - mx1));
        }

        // ---- row sums via ones-vector MMA ----
        float ls[4] = {0.f, 0.f, 0.f, 0.f};
#pragma unroll
        for (int kt = 0; kt < 4; kt++)
            mma16816h(ls, pw0[2 * kt], pw1[2 * kt],
                      pw0[2 * kt + 1], pw1[2 * kt + 1], ONES16X2, ONES16X2);
        l0 += ls[0];
        l1 += ls[2];

        // ---- PV ----
#pragma unroll
        for (int kt = 0; kt < 4; kt++) {
#pragma unroll
            for (int nb = 0; nb < 8; nb++) {
                uint2 vv = *(const uint2*)(vb_ + ((nb << 2) | kt) * 256 + lane * 8);
                mma16816h(oc[nb], pw0[2 * kt], pw1[2 * kt],
                          pw0[2 * kt + 1], pw1[2 * kt + 1], vv.x, vv.y);
            }
        }

        if (ch < 31) __syncthreads();
    }

    // ---- epilogue: write f16 packed-A fragments ----
    const float inv0 = 1.f / l0;
    const float inv1 = 1.f / l1;
    uint32_t* Areg = AOpk + (size_t)(b * 16 + qt) * 32 * 2048;
#pragma unroll
    for (int nb = 0; nb < 8; nb++) {
        int kpair = h * 2 + (nb >> 2);
        int kb = (nb >> 1) & 1;
        uint32_t* base = Areg + (size_t)kpair * 2048 + (wid * 2 + kb) * 128 + lane * 4;
        int i01 = (nb & 1) ? 2 : 0;
        int i23 = (nb & 1) ? 3 : 1;
        base[i01] = pkf16(oc[nb][0] * inv0, oc[nb][1] * inv0);
        base[i23] = pkf16(oc[nb][2] * inv1, oc[nb][3] * inv1);
    }
#undef FA_PREFETCH
}

// ---------------------------------------------------------------------------
// Launch
// ---------------------------------------------------------------------------
extern "C" void kernel_launch(void* const* d_in, const int* in_sizes, int n_in,
                              void* d_out, int out_size)
{
    const float* X   = (const float*)d_in[0];
    const float* R   = (const float*)d_in[1];
    const float* ent = (const float*)d_in[2];
    const float* Wq  = (const float*)d_in[3];
    const float* Wk  = (const float*)d_in[4];
    const float* Wv  = (const float*)d_in[5];
    const float* Wo  = (const float*)d_in[6];
    float* out = (float*)d_out;

    float *rt, *wt;
    uint32_t *kh, *vh, *qpk, *xpk, *aopk, *wfpk, *wopk;
    cudaGetSymbolAddress((void**)&rt,   g_RT);
    cudaGetSymbolAddress((void**)&wt,   g_WT);
    cudaGetSymbolAddress((void**)&kh,   g_Kh);
    cudaGetSymbolAddress((void**)&vh,   g_Vh);
    cudaGetSymbolAddress((void**)&qpk,  g_Qpk);
    cudaGetSymbolAddress((void**)&xpk,  g_Xpk);
    cudaGetSymbolAddress((void**)&aopk, g_AOpk);
    cudaGetSymbolAddress((void**)&wfpk, g_Wfpk);
    cudaGetSymbolAddress((void**)&wopk, g_Wopk);

    static int smem_set = 0;
    if (!smem_set) {
        cudaFuncSetAttribute(fold_gemm_kernel,
                             cudaFuncAttributeMaxDynamicSharedMemorySize, TCB_SMEM);
        cudaFuncSetAttribute(pk_gemm,
                             cudaFuncAttributeMaxDynamicSharedMemorySize, PKG_SMEM);
        smem_set = 1;
    }

    // 1) Transposes: RT = R^T, WT_i = W_i^T
    {
        dim3 g(32, 32, 4);
        transpose_kernel<<<g, 256>>>(R, Wq, Wk, Wv, rt, wt);
    }

    // 2) Folds (batched): Wfold_i = R^T W_i, written directly as packed B
    {
        dim3 g(8, 8, 3);
        fold_gemm_kernel<<<g, 256, TCB_SMEM>>>(rt, wt, wfpk, ent,
                                               (size_t)DD * DD);
    }

    // 3) Pack inputs: X (A-side f16), Wo (B-side split f16)
    pack_a_kernel<<<dim3(32, 32), 256>>>(X, xpk);
    pack_b_kernel<<<dim3(32,  8), 256>>>(Wo, wopk);

    // 4) Fused QKV projection (128x256 tiles); epilogue writes Qpk/Kh/Vh
    {
        dim3 g(12, 32);
        pk_gemm<<<g, 256, PKG_SMEM>>>(xpk, wfpk, out /*unused*/, DD, 1,
                                      qpk, kh, vh);
    }

    // 5) Flash attention (writes f16 packed AO)
    {
        dim3 g(LL / 128, HH, BB);
        flash_attn_tc2<<<g, 256>>>(qpk, kh, vh, aopk);
    }

    // 6) Output projection (128x256 tiles): out = AO @ Wo^T
    {
        dim3 g(4, 32);
        pk_gemm<<<g, 256, PKG_SMEM>>>(aopk, wopk, out, DD, 0, qpk, kh, vh);
    }
}

// round 14
// speedup vs baseline: 1.0437x; 1.0437x over previous
#include <cuda_runtime.h>
#include <cuda_bf16.h>
#include <math.h>
#include <stdint.h>

// Problem constants
#define BB   2
#define LL   2048
#define DD   1024
#define HH   16
#define HD   64
#define MM   (BB*LL)          // 4096

// Scratch (static device memory -- no allocations allowed)
__device__ float g_RT[DD * DD];           // R^T
__device__ float g_WT[3 * DD * DD];       // W_i^T
// fp16 fragment-layout K/V: per (b,h,chunk64) 32 blocks of 256B
__device__ uint32_t g_Kh[BB * HH * 32 * 32 * 64];   // 8MB
__device__ uint32_t g_Vh[BB * HH * 32 * 32 * 64];   // 8MB
// Q in attention A-fragment order: (tile16 0..255, colblk 0..63) x 128 words
__device__ uint32_t g_Qpk[256 * 64 * 128];          // 8MB
// packed GEMM operands
__device__ uint32_t g_Xpk [32 * 32 * 2048];   // X packed f16 (8MB)
__device__ uint32_t g_AOpk[32 * 32 * 2048];   // attention out packed f16 (8MB)
__device__ uint32_t g_Wfpk[24 * 32 * 4096];   // folded W packed hi/lo f16 (12MB)
__device__ uint32_t g_Wopk[ 8 * 32 * 4096];   // Wo packed hi/lo f16 (4MB)

// ===========================================================================
// helpers
// ===========================================================================
__device__ __forceinline__ uint32_t pkf16(float lo, float hi) {
    uint32_t r;
    asm("cvt.rn.f16x2.f32 %0, %1, %2;" : "=r"(r) : "f"(hi), "f"(lo));
    return r;
}

__device__ __forceinline__ void unpkf16(float& lo, float& hi, uint32_t w) {
    asm("{.reg .b16 l, h; mov.b32 {l, h}, %2; cvt.f32.f16 %0, l; cvt.f32.f16 %1, h;}"
        : "=f"(lo), "=f"(hi) : "r"(w));
}

// split two fp32 -> (hi f16x2 word, lo f16x2 word)
__device__ __forceinline__ uint2 split2h(float a, float b) {
    uint32_t h = pkf16(a, b);
    float f0, f1;
    unpkf16(f0, f1, h);
    uint32_t l = pkf16(a - f0, b - f1);
    return make_uint2(h, l);
}

// split fp32x4 -> (hi pair, lo pair)  (pack kernels)
__device__ __forceinline__ uint4 split4h(float4 v) {
    uint32_t h01 = pkf16(v.x, v.y);
    uint32_t h23 = pkf16(v.z, v.w);
    float f0, f1, f2, f3;
    unpkf16(f0, f1, h01);
    unpkf16(f2, f3, h23);
    uint32_t l01 = pkf16(v.x - f0, v.y - f1);
    uint32_t l23 = pkf16(v.z - f2, v.w - f3);
    return make_uint4(h01, h23, l01, l23);
}

// bf16 split (fold GEMM operands)
__device__ __forceinline__ uint4 split4(float4 v) {
    uint32_t h01, h23;
    asm("cvt.rn.bf16x2.f32 %0, %1, %2;" : "=r"(h01) : "f"(v.y), "f"(v.x));
    asm("cvt.rn.bf16x2.f32 %0, %1, %2;" : "=r"(h23) : "f"(v.w), "f"(v.z));
    float h0 = __uint_as_float(h01 << 16);
    float h1 = __uint_as_float(h01 & 0xFFFF0000u);
    float h2 = __uint_as_float(h23 << 16);
    float h3 = __uint_as_float(h23 & 0xFFFF0000u);
    uint32_t l01, l23;
    asm("cvt.rn.bf16x2.f32 %0, %1, %2;" : "=r"(l01) : "f"(v.y - h1), "f"(v.x - h0));
    asm("cvt.rn.bf16x2.f32 %0, %1, %2;" : "=r"(l23) : "f"(v.w - h3), "f"(v.z - h2));
    return make_uint4(h01, h23, l01, l23);
}

__device__ __forceinline__ void mma16816(float* c,
                                         uint32_t a0, uint32_t a1, uint32_t a2, uint32_t a3,
                                         uint32_t b0, uint32_t b1) {
    asm volatile(
        "mma.sync.aligned.m16n8k16.row.col.f32.bf16.bf16.f32 "
        "{%0,%1,%2,%3}, {%4,%5,%6,%7}, {%8,%9}, {%0,%1,%2,%3};"
        : "+f"(c[0]), "+f"(c[1]), "+f"(c[2]), "+f"(c[3])
        : "r"(a0), "r"(a1), "r"(a2), "r"(a3), "r"(b0), "r"(b1));
}

__device__ __forceinline__ void mma16816h(float* c,
                                          uint32_t a0, uint32_t a1, uint32_t a2, uint32_t a3,
                                          uint32_t b0, uint32_t b1) {
    asm volatile(
        "mma.sync.aligned.m16n8k16.row.col.f32.f16.f16.f32 "
        "{%0,%1,%2,%3}, {%4,%5,%6,%7}, {%8,%9}, {%0,%1,%2,%3};"
        : "+f"(c[0]), "+f"(c[1]), "+f"(c[2]), "+f"(c[3])
        : "r"(a0), "r"(a1), "r"(a2), "r"(a3), "r"(b0), "r"(b1));
}

__device__ __forceinline__ float ex2(float x) {
    float r;
    asm("ex2.approx.f32 %0, %1;" : "=f"(r) : "f"(x));
    return r;
}

__device__ __forceinline__ uint32_t ex2h2(uint32_t x) {
    uint32_t r;
    asm("ex2.approx.f16x2 %0, %1;" : "=r"(r) : "r"(x));
    return r;
}

__device__ __forceinline__ uint32_t smem_u32(const void* p) {
    uint32_t a;
    asm("{ .reg .u64 t; cvta.to.shared.u64 t, %1; cvt.u32.u64 %0, t; }"
        : "=r"(a) : "l"(p));
    return a;
}

__device__ __forceinline__ void cp_async16(uint32_t dst, const void* src) {
    asm volatile("cp.async.cg.shared.global [%0], [%1], 16;"
                 :: "r"(dst), "l"(src) : "memory");
}

// ===========================================================================
// Operand pack kernels (inputs only: X and Wo)
// ===========================================================================
__global__ __launch_bounds__(256)
void pack_a_kernel(const float* __restrict__ src, uint32_t* __restrict__ dst)
{
    const int kpair = blockIdx.x, mtile = blockIdx.y, tid = threadIdx.x;
    uint32_t* region = dst + ((size_t)mtile * 32 + kpair) * 2048;
#pragma unroll
    for (int i = 0; i < 4; i++) {
        int idx = i * 256 + tid;
        int row = idx >> 3, c4 = (idx & 7) << 2;
        float4 v = *reinterpret_cast<const float4*>(
            &src[(size_t)(mtile * 128 + row) * 1024 + kpair * 32 + c4]);
        uint32_t w0 = pkf16(v.x, v.y);
        uint32_t w1 = pkf16(v.z, v.w);
        int mb = row >> 4, r = row & 7;
        int islow = ((row & 15) < 8);
        int kb = c4 >> 4, kk = c4 & 15;
        int khigh = (kk >> 3) & 1, t = (kk & 7) >> 1;
        uint32_t* base = region + (mb * 2 + kb) * 128;
        int aidx = islow ? (khigh ? 2 : 0) : (khigh ? 3 : 1);
        base[(r * 4 + t)     * 4 + aidx] = w0;
        base[(r * 4 + t + 1) * 4 + aidx] = w1;
    }
}

__global__ __launch_bounds__(256)
void pack_b_kernel(const float* __restrict__ src, uint32_t* __restrict__ dst)
{
    const int kpair = blockIdx.x, ntile = blockIdx.y, tid = threadIdx.x;
    uint32_t* region = dst + ((size_t)ntile * 32 + kpair) * 4096;
#pragma unroll
    for (int i = 0; i < 4; i++) {
        int idx = i * 256 + tid;
        int row = idx >> 3, c4 = (idx & 7) << 2;
        float4 v = *reinterpret_cast<const float4*>(
            &src[(size_t)(ntile * 128 + row) * 1024 + kpair * 32 + c4]);
        uint4 sp = split4h(v);
        int nb = row >> 3;
        int kb = c4 >> 4, kk = c4 & 15;
        int khigh = (kk >> 3) & 1, t = (kk & 7) >> 1;
        int L = ((row & 7) << 2) + t;
        uint32_t* base = region + (nb * 2 + kb) * 128;
        base[L * 2 + khigh]            = sp.x;
        base[(L + 1) * 2 + khigh]      = sp.y;
        base[64 + L * 2 + khigh]       = sp.z;
        base[64 + (L + 1) * 2 + khigh] = sp.w;
    }
}

// ===========================================================================
// Packed 2-pass f16 GEMM (round-12 config = best): C = A @ (Bhi+Blo)^T.
// 256 thr, 8 warps of 64x32, BK=32, double buffer, 2 CTAs/SM.
// mode 0: fp32 C epilogue; mode 1: QKV fused epilogue -> Qpk/Kh/Vh.
// ===========================================================================
#define PKG_SMEM 49152

__global__ __launch_bounds__(256)
void pk_gemm(const uint32_t* __restrict__ A, const uint32_t* __restrict__ B,
             float* __restrict__ C, int ldc, int mode,
             uint32_t* __restrict__ Qpk, uint32_t* __restrict__ Kh,
             uint32_t* __restrict__ Vh)
{
    extern __shared__ char sm[];
    const uint32_t sb = smem_u32(sm);
    const int tid  = threadIdx.x;
    const int lane = tid & 31;
    const int wid  = tid >> 5;
    const int wm   = (wid >> 2) * 64;
    const int wn   = (wid & 3) * 32;

    const char* Ag = reinterpret_cast<const char*>(A + (size_t)blockIdx.y * 32 * 2048);
    const char* Bg = reinterpret_cast<const char*>(B + (size_t)blockIdx.x * 32 * 4096);

    float acc[4][4][4];
#pragma unroll
    for (int i = 0; i < 4; i++)
#pragma unroll
        for (int j = 0; j < 4; j++)
#pragma unroll
            for (int q = 0; q < 4; q++) acc[i][j][q] = 0.f;

#define PKG_PF(ch)                                                             \
    {                                                                          \
        uint32_t d = sb + ((ch) & 1) * 24576;                                  \
        const char* a = Ag + (size_t)(ch) * 8192 + tid * 32;                   \
        const char* b = Bg + (size_t)(ch) * 16384 + tid * 64;                  \
        cp_async16(d + tid * 32,      a);                                      \
        cp_async16(d + tid * 32 + 16, a + 16);                                 \
        uint32_t db = d + 8192 + tid * 64;                                     \
        cp_async16(db,      b);                                                \
        cp_async16(db + 16, b + 16);                                           \
        cp_async16(db + 32, b + 32);                                           \
        cp_async16(db + 48, b + 48);                                           \
        asm volatile("cp.async.commit_group;" ::: "memory");                   \
    }

    PKG_PF(0);

    for (int ch = 0; ch < 32; ch++) {
        if (ch < 31) {
            PKG_PF(ch + 1);
            asm volatile("cp.async.wait_group 1;" ::: "memory");
        } else {
            asm volatile("cp.async.wait_group 0;" ::: "memory");
        }
        __syncthreads();

        const char* bufA = sm + (ch & 1) * 24576;
        const char* bufB = bufA + 8192;
#pragma unroll
        for (int kb = 0; kb < 2; kb++) {
            uint4 ah[4];
            uint2 bh[4], bl[4];
#pragma unroll
            for (int am = 0; am < 4; am++) {
                const char* p = bufA + ((((wm >> 4) + am) * 2 + kb) << 9) + lane * 16;
                ah[am] = *(const uint4*)p;
            }
#pragma unroll
            for (int bn = 0; bn < 4; bn++) {
                const char* q = bufB + ((((wn >> 3) + bn) * 2 + kb) << 9) + lane * 8;
                bh[bn] = *(const uint2*)q;
                bl[bn] = *(const uint2*)(q + 256);
            }
#pragma unroll
            for (int am = 0; am < 4; am++)
#pragma unroll
                for (int bn = 0; bn < 4; bn++) {
                    float* c = acc[am][bn];
                    mma16816h(c, ah[am].x, ah[am].y, ah[am].z, ah[am].w,
                              bh[bn].x, bh[bn].y);
                    mma16816h(c, ah[am].x, ah[am].y, ah[am].z, ah[am].w,
                              bl[bn].x, bl[bn].y);
                }
        }
        if (ch < 31) __syncthreads();
    }

    const int m0 = blockIdx.y * 128;
    const int n0 = blockIdx.x * 128;

    if (mode == 0) {
#pragma unroll
        for (int am = 0; am < 4; am++)
#pragma unroll
            for (int bn = 0; bn < 4; bn++) {
                const float* c = acc[am][bn];
                int row = m0 + wm + am * 16 + (lane >> 2);
                int col = n0 + wn + bn * 8 + ((lane & 3) << 1);
                *reinterpret_cast<float2*>(&C[(size_t)row * ldc + col]) =
                    make_float2(c[0], c[1]);
                *reinterpret_cast<float2*>(&C[(size_t)(row + 8) * ldc + col]) =
                    make_float2(c[2], c[3]);
            }
    } else if (blockIdx.x < 8) {
        // ---- Q: f16 A-fragment words (scale folded into weights) ----
#pragma unroll
        for (int am = 0; am < 4; am++)
#pragma unroll
            for (int bn = 0; bn < 4; bn++) {
                const float* c = acc[am][bn];
                int row = m0 + wm + am * 16 + (lane >> 2);
                int col = n0 + wn + bn * 8 + ((lane & 3) << 1);
                size_t t16 = (size_t)(row >> 4);
                int cb = col >> 4;
                int bhf = (col >> 3) & 1;
                uint32_t* qd = Qpk + (t16 * 64 + cb) * 128 + lane * 4 + bhf * 2;
                qd[0] = pkf16(c[0], c[1]);
                qd[1] = pkf16(c[2], c[3]);
            }
    } else if (blockIdx.x < 16) {
        // ---- K: attention B-fragment words ----
#pragma unroll
        for (int am = 0; am < 4; am++)
#pragma unroll
            for (int bn = 0; bn < 4; bn++) {
                const float* c = acc[am][bn];
                int row = m0 + wm + am * 16 + (lane >> 2);
                int col = n0 + wn + bn * 8 + ((lane & 3) << 1);
                int bq = row >> 11, seq = row & 2047;
                int chh = seq >> 6, keyl = seq & 63;
                int nk = col - 1024, hh = nk >> 6, d = nk & 63;
                size_t grp = ((size_t)(bq * HH + hh) * 32 + chh) * 32;
                int w = (d >> 3) & 1;
                int L = ((keyl & 7) << 2) | ((d >> 1) & 3);
                Kh[(grp + (keyl >> 3) * 4 + (d >> 4)) * 64 + L * 2 + w] =
                    pkf16(c[0], c[1]);
                Kh[(grp + ((keyl >> 3) + 1) * 4 + (d >> 4)) * 64 + L * 2 + w] =
                    pkf16(c[2], c[3]);
            }
    } else {
        // ---- V: (key, key+1) pairs via shfl_xor(4) ----
#pragma unroll
        for (int am = 0; am < 4; am++)
#pragma unroll
            for (int bn = 0; bn < 4; bn++) {
                const float* c = acc[am][bn];
                float p0 = __shfl_xor_sync(0xffffffffu, c[0], 4);
                float p1 = __shfl_xor_sync(0xffffffffu, c[1], 4);
                float p2 = __shfl_xor_sync(0xffffffffu, c[2], 4);
                float p3 = __shfl_xor_sync(0xffffffffu, c[3], 4);
                if (!(lane & 4)) {
                    int row = m0 + wm + am * 16 + (lane >> 2);
                    int col = n0 + wn + bn * 8 + ((lane & 3) << 1);
                    int bq = row >> 11, seq = row & 2047;
                    int chh = seq >> 6, keyl = seq & 63;
                    int nv = col - 2048, hh = nv >> 6, d = nv & 63;
                    size_t grp = ((size_t)(bq * HH + hh) * 32 + chh) * 32;
                    int kp = keyl >> 1;
                    int L = ((d & 7) << 2) | (kp & 3);
                    int w = (kp & 7) >> 2;
                    size_t blk = (grp + (d >> 3) * 4 + (keyl >> 4)) * 64;
                    Vh[blk + L * 2 + w]             = pkf16(c[0], p0);
                    Vh[blk + (L + 4) * 2 + w]       = pkf16(c[1], p1);
                    Vh[blk + L * 2 + (w ^ 1)]       = pkf16(c[2], p2);
                    Vh[blk + (L + 4) * 2 + (w ^ 1)] = pkf16(c[3], p3);
                }
            }
    }
#undef PKG_PF
}

// ===========================================================================
// Fold GEMM (convert-in-kernel split-bf16): C = R^T W_i, epilogue writes
// split-f16 packed-B words directly; Wq rows get the softmax scale folded in.
// ===========================================================================
#define TCB_SMEM 65536

__global__ __launch_bounds__(256, 1)
void fold_gemm_kernel(const float* __restrict__ A, const float* __restrict__ B,
                      uint32_t* __restrict__ Bpk, const float* __restrict__ ent,
                      size_t sB)
{
    extern __shared__ char sm[];
    B += blockIdx.z * sB;
    const int tid  = threadIdx.x;
    const int lane = tid & 31;
    const int wid  = tid >> 5;
    const int wm   = (wid >> 2) * 64;
    const int wn   = (wid & 3) * 32;
    const int m0 = blockIdx.y * 128;
    const int n0 = blockIdx.x * 128;
    const int pl = lane ^ (lane >> 3);

    float acc[4][4][4];
#pragma unroll
    for (int i = 0; i < 4; i++)
#pragma unroll
        for (int j = 0; j < 4; j++)
#pragma unroll
            for (int q = 0; q < 4; q++) acc[i][j][q] = 0.f;

    float4 ra[4], rb[4];

#define LDG_CHUNK(k0)                                                          \
    {                                                                          \
        _Pragma("unroll")                                                      \
        for (int i = 0; i < 4; i++) {                                          \
            int idx = i * 256 + tid;                                           \
            int r = idx >> 3, c4 = (idx & 7) << 2;                             \
            ra[i] = *reinterpret_cast<const float4*>(                          \
                &A[(size_t)(m0 + r) * 1024 + (k0) + c4]);                      \
            rb[i] = *reinterpret_cast<const float4*>(                          \
                &B[(size_t)(n0 + r) * 1024 + (k0) + c4]);                      \
        }                                                                      \
    }

#define STS_CHUNK(bufp)                                                        \
    {                                                                          \
        char* _buf = (bufp);                                                   \
        _Pragma("unroll")                                                      \
        for (int i = 0; i < 4; i++) {                                          \
            int idx = i * 256 + tid;                                           \
            int r = idx >> 3, c4 = (idx & 7) << 2;                             \
            int kb = c4 >> 4, kk = c4 & 15;                                    \
            int rr = r & 15, mb = r >> 4;                                      \
            int s  = ((rr & 7) << 2) + ((kk & 7) >> 1);                        \
            int ps  = s ^ (s >> 3);                                            \
            int ps1 = (s + 1) ^ ((s + 1) >> 3);                                \
            int rg = (kk >> 3) + ((rr >> 3) << 1);                             \
            uint4 sp = split4(ra[i]);                                          \
            char* ab = _buf + (((mb << 1) + kb) << 9) + (rg << 2);             \
            *(uint32_t*)(ab + ps  * 16)        = sp.x;                         \
            *(uint32_t*)(ab + ps1 * 16)        = sp.y;                         \
            *(uint32_t*)(ab + 8192 + ps  * 16) = sp.z;                         \
            *(uint32_t*)(ab + 8192 + ps1 * 16) = sp.w;                         \
            int nn = r & 7, nb = r >> 3;                                       \
            int sb2 = (nn << 2) + ((kk & 7) >> 1);                             \
            int psb  = sb2 ^ (sb2 >> 3);                                       \
            int psb1 = (sb2 + 1) ^ ((sb2 + 1) >> 3);                           \
            int rgb = kk >> 3;                                                 \
            uint4 sq = split4(rb[i]);                                          \
            char* bb = _buf + 16384 + (((nb << 1) + kb) << 9) + (rgb << 2);    \
            *(uint32_t*)(bb + psb  * 16)     = sq.x;                           \
            *(uint32_t*)(bb + psb1 * 16)     = sq.y;                           \
            *(uint32_t*)(bb + psb  * 16 + 8) = sq.z;                           \
            *(uint32_t*)(bb + psb1 * 16 + 8) = sq.w;                           \
        }                                                                      \
    }

#define COMPUTE_CHUNK(bufp)                                                    \
    {                                                                          \
        const char* _buf = (bufp);                                             \
        _Pragma("unroll")                                                      \
        for (int kb = 0; kb < 2; kb++) {                                       \
            uint4 ah[4], al[4], bq[4];                                         \
            _Pragma("unroll")                                                  \
            for (int am = 0; am < 4; am++) {                                   \
                const char* p = _buf + (((((wm >> 4) + am) << 1) + kb) << 9)   \
                                + pl * 16;                                     \
                ah[am] = *(const uint4*)p;                                     \
                al[am] = *(const uint4*)(p + 8192);                            \
            }                                                                  \
            _Pragma("unroll")                                                  \
            for (int bn = 0; bn < 4; bn++) {                                   \
                const char* p = _buf + 16384                                   \
                                + (((((wn >> 3) + bn) << 1) + kb) << 9)        \
                                + pl * 16;                                     \
                bq[bn] = *(const uint4*)p;                                     \
            }                                                                  \
            _Pragma("unroll")                                                  \
            for (int am = 0; am < 4; am++)                                     \
                _Pragma("unroll")                                              \
                for (int bn = 0; bn < 4; bn++) {                               \
                    float* c = acc[am][bn];                                    \
                    mma16816(c, ah[am].x, ah[am].z, ah[am].y, ah[am].w,        \
                             bq[bn].x, bq[bn].y);                              \
                    mma16816(c, ah[am].x, ah[am].z, ah[am].y, ah[am].w,        \
                             bq[bn].z, bq[bn].w);                              \
                    mma16816(c, al[am].x, al[am].z, al[am].y, al[am].w,        \
                             bq[bn].x, bq[bn].y);                              \
                }                                                              \
        }                                                                      \
    }

    LDG_CHUNK(0);
    STS_CHUNK(sm);
    __syncthreads();

    for (int ch = 0; ch < 32; ch++) {
        if (ch < 31) LDG_CHUNK((ch + 1) * 32);
        COMPUTE_CHUNK(sm + (ch & 1) * 32768);
        if (ch < 31) {
            STS_CHUNK(sm + ((ch + 1) & 1) * 32768);
            __syncthreads();
        }
    }

    // ---- epilogue: write split-f16 packed-B words (rows = neurons, cols = k)
#pragma unroll
    for (int am = 0; am < 4; am++)
#pragma unroll
        for (int bn = 0; bn < 4; bn++) {
            const float* c = acc[am][bn];
            int row = m0 + wm + am * 16 + (lane >> 2);
            int col = n0 + wn + bn * 8 + ((lane & 3) << 1);
            float s = 1.f;
            if (blockIdx.z == 0) s = ent[row >> 6] * 0.125f * 1.44269504f;
            int ntg = blockIdx.z * 8 + (row >> 7);
            int kpair = col >> 5;
            uint32_t* region = Bpk + ((size_t)ntg * 32 + kpair) * 4096;
            int kb = (col >> 4) & 1;
            int khigh = (col >> 3) & 1;
            int t = (col >> 1) & 3;
            int L = ((row & 7) << 2) + t;
            {
                uint2 u = split2h(c[0] * s, c[1] * s);
                uint32_t* base = region + (((row >> 3) & 15) * 2 + kb) * 128;
                base[L * 2 + khigh]      = u.x;
                base[64 + L * 2 + khigh] = u.y;
            }
            {
                uint2 u = split2h(c[2] * s, c[3] * s);
                uint32_t* base = region + ((((row + 8) >> 3) & 15) * 2 + kb) * 128;
                base[L * 2 + khigh]      = u.x;
                base[64 + L * 2 + khigh] = u.y;
            }
        }
#undef LDG_CHUNK
#undef STS_CHUNK
#undef COMPUTE_CHUNK
}

// ---------------------------------------------------------------------------
// Batched 1024x1024 transpose: z=0 -> RT = R^T; z=1..3 -> WT_i = W_i^T
// ---------------------------------------------------------------------------
__global__ __launch_bounds__(256)
void transpose_kernel(const float* __restrict__ R,
                      const float* __restrict__ Wq,
                      const float* __restrict__ Wk,
                      const float* __restrict__ Wv,
                      float* __restrict__ RT, float* __restrict__ WT)
{
    __shared__ float t[32][33];
    const int z = blockIdx.z;
    const float* src = (z == 0) ? R : (z == 1) ? Wq : (z == 2) ? Wk : Wv;
    float* dst = (z == 0) ? RT : (WT + (size_t)(z - 1) * DD * DD);

    const int x0 = blockIdx.x * 32;
    const int y0 = blockIdx.y * 32;
    const int tx = threadIdx.x & 31;
    const int ty = threadIdx.x >> 5;

#pragma unroll
    for (int i = 0; i < 4; i++)
        t[ty + i * 8][tx] = src[(size_t)(y0 + ty + i * 8) * DD + x0 + tx];
    __syncthreads();
#pragma unroll
    for (int i = 0; i < 4; i++)
        dst[(size_t)(x0 + ty + i * 8) * DD + y0 + tx] = t[tx][ty + i * 8];
}

// ===========================================================================
// Tensor-core flash attention: 128-key pipeline stages (two 64-key
// sub-iterations per prefetch/barrier pair), double-buffered 32KB stages.
// Softmax-lite, lazy rescale. Writes f16 packed-A AO.
// ===========================================================================
#define ONES16X2 0x3C003C00u
#define FA_STAGE 32768          // 16KB K + 16KB V (2 x 64-key chunks)
#define FA_SMEM  (2 * FA_STAGE) // 65536

__global__ __launch_bounds__(256, 2)
void flash_attn_tc2(const uint32_t* __restrict__ Qpk,
                    const uint32_t* __restrict__ Kh,
                    const uint32_t* __restrict__ Vh,
                    uint32_t* __restrict__ AOpk)
{
    extern __shared__ char sbuf[];
    const uint32_t sb0 = smem_u32(sbuf);

    const int b  = blockIdx.z;
    const int h  = blockIdx.y;
    const int qt = blockIdx.x;
    const int tid  = threadIdx.x;
    const int lane = tid & 31;
    const int wid  = tid >> 5;

    // ---- Q fragments: 4 x LDG.128, already scaled ----
    uint32_t qa[4][4];
    {
        const uint32_t* qbase =
            Qpk + ((size_t)(b * 128 + qt * 8 + wid) * 64 + h * 4) * 128 + lane * 4;
#pragma unroll
        for (int kb = 0; kb < 4; kb++)
            *reinterpret_cast<uint4*>(qa[kb]) =
                *reinterpret_cast<const uint4*>(qbase + kb * 128);
    }

    float oc[8][4];
#pragma unroll
    for (int i = 0; i < 8; i++)
#pragma unroll
        for (int j = 0; j < 4; j++) oc[i][j] = 0.f;
    float l0 = 0.f, l1 = 0.f;
    float mx0 = -1e30f, mx1 = -1e30f;

    const char* Kg = reinterpret_cast<const char*>(Kh)
                     + (size_t)((b * HH + h) * 32) * 8192;
    const char* Vg = reinterpret_cast<const char*>(Vh)
                     + (size_t)((b * HH + h) * 32) * 8192;

    // stage g covers key chunks 2g, 2g+1 (contiguous 16KB in Kg / Vg)
#define FA_PREFETCH(g)                                                         \
    {                                                                          \
        uint32_t d = sb0 + ((g) & 1) * FA_STAGE + tid * 16;                    \
        const char* ks = Kg + (size_t)(g) * 16384 + tid * 16;                  \
        const char* vs = Vg + (size_t)(g) * 16384 + tid * 16;                  \
        cp_async16(d,            ks);                                          \
        cp_async16(d + 4096,     ks + 4096);                                   \
        cp_async16(d + 8192,     ks + 8192);                                   \
        cp_async16(d + 12288,    ks + 12288);                                  \
        cp_async16(d + 16384,    vs);                                          \
        cp_async16(d + 20480,    vs + 4096);                                   \
        cp_async16(d + 24576,    vs + 8192);                                   \
        cp_async16(d + 28672,    vs + 12288);                                  \
        asm volatile("cp.async.commit_group;" ::: "memory");                   \
    }

    FA_PREFETCH(0);

    for (int g = 0; g < 16; g++) {
        if (g < 15) {
            FA_PREFETCH(g + 1);
            asm volatile("cp.async.wait_group 1;" ::: "memory");
        } else {
            asm volatile("cp.async.wait_group 0;" ::: "memory");
        }
        __syncthreads();

        const char* stage = sbuf + (g & 1) * FA_STAGE;

#pragma unroll
        for (int s = 0; s < 2; s++) {
            const char* kb_ = stage + s * 8192;
            const char* vb_ = stage + 16384 + s * 8192;

            // ---- QK ----
            float sc[8][4];
#pragma unroll
            for (int nb = 0; nb < 8; nb++) {
                sc[nb][0] = sc[nb][1] = sc[nb][2] = sc[nb][3] = 0.f;
#pragma unroll
                for (int kb = 0; kb < 4; kb++) {
                    uint2 bb = *(const uint2*)(kb_ + ((nb << 2) | kb) * 256 + lane * 8);
                    mma16816h(sc[nb], qa[kb][0], qa[kb][1], qa[kb][2], qa[kb][3],
                              bb.x, bb.y);
                }
            }

            // ---- max reduce ----
            float cm0 = mx0, cm1 = mx1;
#pragma unroll
            for (int nb = 0; nb < 8; nb++) {
                cm0 = fmaxf(cm0, fmaxf(sc[nb][0], sc[nb][1]));
                cm1 = fmaxf(cm1, fmaxf(sc[nb][2], sc[nb][3]));
            }
            cm0 = fmaxf(cm0, __shfl_xor_sync(0xffffffffu, cm0, 1));
            cm0 = fmaxf(cm0, __shfl_xor_sync(0xffffffffu, cm0, 2));
            cm1 = fmaxf(cm1, __shfl_xor_sync(0xffffffffu, cm1, 1));
            cm1 = fmaxf(cm1, __shfl_xor_sync(0xffffffffu, cm1, 2));

            // ---- lazy rescale ----
            if (__any_sync(0xffffffffu, (cm0 > mx0) || (cm1 > mx1))) {
                float corr0 = ex2(mx0 - cm0), corr1 = ex2(mx1 - cm1);
                mx0 = cm0; mx1 = cm1;
                l0 *= corr0; l1 *= corr1;
#pragma unroll
                for (int nb = 0; nb < 8; nb++) {
                    oc[nb][0] *= corr0; oc[nb][1] *= corr0;
                    oc[nb][2] *= corr1; oc[nb][3] *= corr1;
                }
            }

            // ---- P fragments via f16x2 ex2 ----
            uint32_t pw0[8], pw1[8];
#pragma unroll
            for (int nb = 0; nb < 8; nb++) {
                pw0[nb] = ex2h2(pkf16(sc[nb][0] - mx0, sc[nb][1] - mx0));
                pw1[nb] = ex2h2(pkf16(sc[nb][2] - mx1, sc[nb][3] - mx1));
            }

            // ---- row sums via ones-vector MMA ----
            float ls[4] = {0.f, 0.f, 0.f, 0.f};
#pragma unroll
            for (int kt = 0; kt < 4; kt++)
                mma16816h(ls, pw0[2 * kt], pw1[2 * kt],
                          pw0[2 * kt + 1], pw1[2 * kt + 1], ONES16X2, ONES16X2);
            l0 += ls[0];
            l1 += ls[2];

            // ---- PV ----
#pragma unroll
            for (int kt = 0; kt < 4; kt++) {
#pragma unroll
                for (int nb = 0; nb < 8; nb++) {
                    uint2 vv = *(const uint2*)(vb_ + ((nb << 2) | kt) * 256 + lane * 8);
                    mma16816h(oc[nb], pw0[2 * kt], pw1[2 * kt],
                              pw0[2 * kt + 1], pw1[2 * kt + 1], vv.x, vv.y);
                }
            }
        }

        if (g < 15) __syncthreads();
    }

    // ---- epilogue: write f16 packed-A fragments ----
    const float inv0 = 1.f / l0;
    const float inv1 = 1.f / l1;
    uint32_t* Areg = AOpk + (size_t)(b * 16 + qt) * 32 * 2048;
#pragma unroll
    for (int nb = 0; nb < 8; nb++) {
        int kpair = h * 2 + (nb >> 2);
        int kb = (nb >> 1) & 1;
        uint32_t* base = Areg + (size_t)kpair * 2048 + (wid * 2 + kb) * 128 + lane * 4;
        int i01 = (nb & 1) ? 2 : 0;
        int i23 = (nb & 1) ? 3 : 1;
        base[i01] = pkf16(oc[nb][0] * inv0, oc[nb][1] * inv0);
        base[i23] = pkf16(oc[nb][2] * inv1, oc[nb][3] * inv1);
    }
#undef FA_PREFETCH
}

// ---------------------------------------------------------------------------
// Launch
// ---------------------------------------------------------------------------
extern "C" void kernel_launch(void* const* d_in, const int* in_sizes, int n_in,
                              void* d_out, int out_size)
{
    const float* X   = (const float*)d_in[0];
    const float* R   = (const float*)d_in[1];
    const float* ent = (const float*)d_in[2];
    const float* Wq  = (const float*)d_in[3];
    const float* Wk  = (const float*)d_in[4];
    const float* Wv  = (const float*)d_in[5];
    const float* Wo  = (const float*)d_in[6];
    float* out = (float*)d_out;

    float *rt, *wt;
    uint32_t *kh, *vh, *qpk, *xpk, *aopk, *wfpk, *wopk;
    cudaGetSymbolAddress((void**)&rt,   g_RT);
    cudaGetSymbolAddress((void**)&wt,   g_WT);
    cudaGetSymbolAddress((void**)&kh,   g_Kh);
    cudaGetSymbolAddress((void**)&vh,   g_Vh);
    cudaGetSymbolAddress((void**)&qpk,  g_Qpk);
    cudaGetSymbolAddress((void**)&xpk,  g_Xpk);
    cudaGetSymbolAddress((void**)&aopk, g_AOpk);
    cudaGetSymbolAddress((void**)&wfpk, g_Wfpk);
    cudaGetSymbolAddress((void**)&wopk, g_Wopk);

    static int smem_set = 0;
    if (!smem_set) {
        cudaFuncSetAttribute(fold_gemm_kernel,
                             cudaFuncAttributeMaxDynamicSharedMemorySize, TCB_SMEM);
        cudaFuncSetAttribute(pk_gemm,
                             cudaFuncAttributeMaxDynamicSharedMemorySize, PKG_SMEM);
        cudaFuncSetAttribute(flash_attn_tc2,
                             cudaFuncAttributeMaxDynamicSharedMemorySize, FA_SMEM);
        smem_set = 1;
    }

    // 1) Transposes: RT = R^T, WT_i = W_i^T
    {
        dim3 g(32, 32, 4);
        transpose_kernel<<<g, 256>>>(R, Wq, Wk, Wv, rt, wt);
    }

    // 2) Folds (batched): Wfold_i = R^T W_i, written directly as packed B
    {
        dim3 g(8, 8, 3);
        fold_gemm_kernel<<<g, 256, TCB_SMEM>>>(rt, wt, wfpk, ent,
                                               (size_t)DD * DD);
    }

    // 3) Pack inputs: X (A-side f16), Wo (B-side split f16)
    pack_a_kernel<<<dim3(32, 32), 256>>>(X, xpk);
    pack_b_kernel<<<dim3(32,  8), 256>>>(Wo, wopk);

    // 4) Fused QKV projection; epilogue writes Qpk / Kh / Vh directly
    {
        dim3 g(24, 32);
        pk_gemm<<<g, 256, PKG_SMEM>>>(xpk, wfpk, out /*unused*/, DD, 1,
                                      qpk, kh, vh);
    }

    // 5) Flash attention (128-key stages, writes f16 packed AO)
    {
        dim3 g(LL / 128, HH, BB);
        flash_attn_tc2<<<g, 256, FA_SMEM>>>(qpk, kh, vh, aopk);
    }

    // 6) Output projection: out = AO @ Wo^T
    {
        dim3 g(8, 32);
        pk_gemm<<<g, 256, PKG_SMEM>>>(aopk, wopk, out, DD, 0, qpk, kh, vh);
    }
}